// round 13
// baseline (speedup 1.0000x reference)
#include <cuda_runtime.h>
#include <cuda_bf16.h>
#include <math.h>

// ---------------------------------------------------------------------------
// Problem constants
// ---------------------------------------------------------------------------
constexpr int kB  = 32, kC = 3, kH = 224, kW = 224;
constexpr int kHW = kH * kW;          // 50176
constexpr int kS  = 256, kD = 768, kL = 12, kNH = 12, kHD = 64;
constexpr int kMLP = 3072, kNC = 1000;
constexpr int kN  = kS + 1;           // 257 tokens
constexpr int kM  = kB * kN;          // 8224 rows
constexpr int kQKV = 3 * kD;          // 2304

// ---------------------------------------------------------------------------
// Scratch (static device globals)
// ---------------------------------------------------------------------------
__device__ float g_x[kM * kD];
__device__ float g_qkv[kM * kQKV];
__device__ float g_seg[kB * kS * kC];
__device__ float g_cls[kB * kD];

// split (bf16 hi/lo) activation buffers
__device__ __nv_bfloat16 g_ah[kM * kD],   g_al[kM * kD];     // LN outputs
__device__ __nv_bfloat16 g_atth[kM * kD], g_attl[kM * kD];   // attention out
__device__ __nv_bfloat16 g_mlph[kM * kMLP], g_mlpl[kM * kMLP]; // gelu out

// split weights (per full [L, ...] tensors)
__device__ __nv_bfloat16 g_wqkvh[kL * kD * kQKV], g_wqkvl[kL * kD * kQKV];
__device__ __nv_bfloat16 g_wprojh[kL * kD * kD],  g_wprojl[kL * kD * kD];
__device__ __nv_bfloat16 g_wm1h[kL * kD * kMLP],  g_wm1l[kL * kD * kMLP];
__device__ __nv_bfloat16 g_wm2h[kL * kMLP * kD],  g_wm2l[kL * kMLP * kD];

// ---------------------------------------------------------------------------
// Helpers
// ---------------------------------------------------------------------------
__device__ __forceinline__ float gelu_exact(float x) {
    return 0.5f * x * (1.0f + erff(x * 0.70710678118654752440f));
}

// bf16 m16n8k16 MMA, fp32 accumulate
__device__ __forceinline__ void mma_bf16(float c[4], const unsigned a[4], const unsigned b[2]) {
    asm volatile(
        "mma.sync.aligned.m16n8k16.row.col.f32.bf16.bf16.f32 "
        "{%0,%1,%2,%3}, {%4,%5,%6,%7}, {%8,%9}, {%0,%1,%2,%3};\n"
        : "+f"(c[0]), "+f"(c[1]), "+f"(c[2]), "+f"(c[3])
        : "r"(a[0]), "r"(a[1]), "r"(a[2]), "r"(a[3]), "r"(b[0]), "r"(b[1]));
}

// ---------------------------------------------------------------------------
// 0) Weight split: h = bf16(v), l = bf16(v - h).  n must be multiple of 4.
// ---------------------------------------------------------------------------
__global__ void wsplit_kernel(const float* __restrict__ w,
                              __nv_bfloat16* __restrict__ h,
                              __nv_bfloat16* __restrict__ l, int n4) {
    const int i = blockIdx.x * blockDim.x + threadIdx.x;
    if (i >= n4) return;
    const float4 v = *(const float4*)(w + (size_t)i * 4);
    float vv[4] = {v.x, v.y, v.z, v.w};
    __nv_bfloat16 hh[4], ll[4];
    #pragma unroll
    for (int j = 0; j < 4; j++) {
        hh[j] = __float2bfloat16(vv[j]);
        ll[j] = __float2bfloat16(vv[j] - __bfloat162float(hh[j]));
    }
    *(__nv_bfloat162*)(h + (size_t)i * 4)     = __nv_bfloat162{hh[0], hh[1]};
    *(__nv_bfloat162*)(h + (size_t)i * 4 + 2) = __nv_bfloat162{hh[2], hh[3]};
    *(__nv_bfloat162*)(l + (size_t)i * 4)     = __nv_bfloat162{ll[0], ll[1]};
    *(__nv_bfloat162*)(l + (size_t)i * 4 + 2) = __nv_bfloat162{ll[2], ll[3]};
}

// ---------------------------------------------------------------------------
// 1) Superpixel segment sums
// ---------------------------------------------------------------------------
__global__ void seg_sum_kernel(const float* __restrict__ img, const int* __restrict__ seg) {
    __shared__ float sm[kS * kC];
    const int b = blockIdx.x;
    for (int i = threadIdx.x; i < kS * kC; i += blockDim.x) sm[i] = 0.f;
    __syncthreads();
    const int*   sb = seg + (size_t)b * kHW;
    const float* i0 = img + (size_t)(b * kC + 0) * kHW;
    const float* i1 = img + (size_t)(b * kC + 1) * kHW;
    const float* i2 = img + (size_t)(b * kC + 2) * kHW;
    for (int p = threadIdx.x; p < kHW; p += blockDim.x) {
        int s = sb[p];
        atomicAdd(&sm[s * 3 + 0], i0[p]);
        atomicAdd(&sm[s * 3 + 1], i1[p]);
        atomicAdd(&sm[s * 3 + 2], i2[p]);
    }
    __syncthreads();
    for (int i = threadIdx.x; i < kS * kC; i += blockDim.x) g_seg[b * kS * kC + i] = sm[i];
}

// ---------------------------------------------------------------------------
// 2) Embedding build
// ---------------------------------------------------------------------------
__global__ void embed_kernel(const float* __restrict__ w_fe, const float* __restrict__ b_fe,
                             const float* __restrict__ cls_t, const float* __restrict__ pos) {
    const int tok = blockIdx.x;
    const int b = tok / kN, n = tok % kN;
    float s0 = 0.f, s1 = 0.f, s2 = 0.f;
    if (n > 0) {
        const float* sp = g_seg + (size_t)(b * kS + (n - 1)) * 3;
        const float inv = 1.0f / (float)kHW;
        s0 = sp[0] * inv; s1 = sp[1] * inv; s2 = sp[2] * inv;
    }
    float* xr = g_x + (size_t)tok * kD;
    for (int d = threadIdx.x; d < kD; d += blockDim.x) {
        float pv = pos[n * kD + d];
        float v;
        if (n == 0) v = cls_t[d] + pv;
        else        v = b_fe[d] + pv + s0 * w_fe[d] + s1 * w_fe[kD + d] + s2 * w_fe[2 * kD + d];
        xr[d] = v;
    }
}

// ---------------------------------------------------------------------------
// 3) LayerNorm.  SPLIT=true -> writes bf16 hi/lo; else fp32.
// ---------------------------------------------------------------------------
template <bool SPLIT>
__global__ __launch_bounds__(256) void ln_kernel(const float* __restrict__ x, float* __restrict__ y,
                          __nv_bfloat16* __restrict__ yh, __nv_bfloat16* __restrict__ yl,
                          const float* __restrict__ gw, const float* __restrict__ bw,
                          long xstride) {
    const int row = blockIdx.x;
    const float* xr = x + (long)row * xstride;
    const int tid = threadIdx.x;
    float v0 = xr[tid], v1 = xr[tid + 256], v2 = xr[tid + 512];
    __shared__ float red[8];

    float s = v0 + v1 + v2;
    #pragma unroll
    for (int o = 16; o > 0; o >>= 1) s += __shfl_down_sync(0xffffffffu, s, o);
    if ((tid & 31) == 0) red[tid >> 5] = s;
    __syncthreads();
    if (tid < 8) {
        float t = red[tid];
        #pragma unroll
        for (int o = 4; o > 0; o >>= 1) t += __shfl_down_sync(0xffu, t, o);
        if (tid == 0) red[0] = t;
    }
    __syncthreads();
    const float m = red[0] * (1.0f / kD);
    __syncthreads();

    const float d0 = v0 - m, d1 = v1 - m, d2 = v2 - m;
    float q = d0 * d0 + d1 * d1 + d2 * d2;
    #pragma unroll
    for (int o = 16; o > 0; o >>= 1) q += __shfl_down_sync(0xffffffffu, q, o);
    if ((tid & 31) == 0) red[tid >> 5] = q;
    __syncthreads();
    if (tid < 8) {
        float t = red[tid];
        #pragma unroll
        for (int o = 4; o > 0; o >>= 1) t += __shfl_down_sync(0xffu, t, o);
        if (tid == 0) red[0] = t;
    }
    __syncthreads();
    const float inv = rsqrtf(red[0] * (1.0f / kD) + 1e-6f);

    float yv[3];
    yv[0] = d0 * inv * gw[tid]       + bw[tid];
    yv[1] = d1 * inv * gw[tid + 256] + bw[tid + 256];
    yv[2] = d2 * inv * gw[tid + 512] + bw[tid + 512];

    if (SPLIT) {
        #pragma unroll
        for (int j = 0; j < 3; j++) {
            const long idx = (long)row * kD + tid + j * 256;
            __nv_bfloat16 h = __float2bfloat16(yv[j]);
            yh[idx] = h;
            yl[idx] = __float2bfloat16(yv[j] - __bfloat162float(h));
        }
    } else {
        y[(long)row * kD + tid]       = yv[0];
        y[(long)row * kD + tid + 256] = yv[1];
        y[(long)row * kD + tid + 512] = yv[2];
    }
}

// ---------------------------------------------------------------------------
// 4) Split-bf16 GEMM with pre-split global operands (pure-copy staging).
//    BM=BN=128, BK=32, 256 threads, warp tile 32x64, m16n8k16 hi/lo 3-term.
//    smem per buffer (u32): Ah[128][20] 2560 | Al 2560 | Bh[16][136] 2176 |
//    Bl 2176 = 9472.  Double buffered = 75776 B; 2 CTAs/SM.
//    OP: 0 = +bias -> fp32 Cout      (QKV)
//        1 = +bias, gelu -> bf16 split Oh/Ol   (MLP1)
//        2 = +bias, +res -> fp32 Cout (proj / MLP2)
// ---------------------------------------------------------------------------
constexpr int BUF_U32   = 9472;
constexpr int GEMM_SMEM = 2 * BUF_U32 * 4;   // 75776 B

template <int OP>
__global__ __launch_bounds__(256, 2) void gemm_kernel(
    const __nv_bfloat16* __restrict__ Ah_g, const __nv_bfloat16* __restrict__ Al_g,
    const __nv_bfloat16* __restrict__ Wh_g, const __nv_bfloat16* __restrict__ Wl_g,
    const float* __restrict__ bias, const float* __restrict__ res,
    float* __restrict__ Cout,
    __nv_bfloat16* __restrict__ Oh, __nv_bfloat16* __restrict__ Ol,
    int M, int N, int K)
{
    extern __shared__ unsigned smemu[];

    const int tid = threadIdx.x;
    const int wid = tid >> 5, lane = tid & 31;
    const int gp = lane >> 2, tg = lane & 3;
    const int wm = (wid >> 1) * 32;     // 4 warps along M
    const int wn = (wid & 1) * 64;      // 2 warps along N
    const int m0 = blockIdx.y * 128;
    const int n0 = blockIdx.x * 128;

    float c[2][8][4];
    #pragma unroll
    for (int i = 0; i < 2; i++)
        #pragma unroll
        for (int j = 0; j < 8; j++)
            #pragma unroll
            for (int r = 0; r < 4; r++) c[i][j][r] = 0.f;

    // loader indices
    const int arow = tid >> 1, ahalf = tid & 1;   // A: row, 16-elem k-half
    const int bq   = tid >> 4, bg    = tid & 15;  // B: k-pair row q, 8-n group

    uint4 apf_h[2], apf_l[2];       // A: 2x16B = 32 bf16 (16 k-elems x hi/lo)
    uint4 bpf_h[2], bpf_l[2];       // B: rows 2q, 2q+1 (8 n each) x hi/lo

    const int nK = K >> 5;

    auto prefetch = [&](int k0) {
        const int grow = m0 + arow;
        if (grow < M) {
            const size_t ga = (size_t)grow * K + k0 + ahalf * 16;
            apf_h[0] = *(const uint4*)(Ah_g + ga);
            apf_h[1] = *(const uint4*)(Ah_g + ga + 8);
            apf_l[0] = *(const uint4*)(Al_g + ga);
            apf_l[1] = *(const uint4*)(Al_g + ga + 8);
        } else {
            apf_h[0] = apf_h[1] = apf_l[0] = apf_l[1] = make_uint4(0, 0, 0, 0);
        }
        const size_t gb = (size_t)(k0 + 2 * bq) * N + n0 + bg * 8;
        bpf_h[0] = *(const uint4*)(Wh_g + gb);
        bpf_h[1] = *(const uint4*)(Wh_g + gb + N);
        bpf_l[0] = *(const uint4*)(Wl_g + gb);
        bpf_l[1] = *(const uint4*)(Wl_g + gb + N);
    };

    auto store_buf = [&](int buf) {
        unsigned* Ah = smemu + buf * BUF_U32;
        unsigned* Al = Ah + 2560;
        unsigned* Bh = Ah + 5120;
        unsigned* Bl = Ah + 7296;
        // A: straight copy (u32 j already = bf16 pair (k=2j, 2j+1))
        *(uint4*)(Ah + arow * 20 + ahalf * 8)     = apf_h[0];
        *(uint4*)(Ah + arow * 20 + ahalf * 8 + 4) = apf_h[1];
        *(uint4*)(Al + arow * 20 + ahalf * 8)     = apf_l[0];
        *(uint4*)(Al + arow * 20 + ahalf * 8 + 4) = apf_l[1];
        // B: interleave rows 2q (lo16) and 2q+1 (hi16) per n
        unsigned oh[8], ol[8];
        const unsigned* ra = (const unsigned*)&bpf_h[0];
        const unsigned* rb = (const unsigned*)&bpf_h[1];
        const unsigned* la = (const unsigned*)&bpf_l[0];
        const unsigned* lb = (const unsigned*)&bpf_l[1];
        #pragma unroll
        for (int j = 0; j < 4; j++) {
            oh[2 * j]     = __byte_perm(ra[j], rb[j], 0x5410);
            oh[2 * j + 1] = __byte_perm(ra[j], rb[j], 0x7632);
            ol[2 * j]     = __byte_perm(la[j], lb[j], 0x5410);
            ol[2 * j + 1] = __byte_perm(la[j], lb[j], 0x7632);
        }
        *(uint4*)(Bh + bq * 136 + bg * 8)     = make_uint4(oh[0], oh[1], oh[2], oh[3]);
        *(uint4*)(Bh + bq * 136 + bg * 8 + 4) = make_uint4(oh[4], oh[5], oh[6], oh[7]);
        *(uint4*)(Bl + bq * 136 + bg * 8)     = make_uint4(ol[0], ol[1], ol[2], ol[3]);
        *(uint4*)(Bl + bq * 136 + bg * 8 + 4) = make_uint4(ol[4], ol[5], ol[6], ol[7]);
    };

    prefetch(0);
    store_buf(0);
    __syncthreads();

    for (int kt = 0; kt < nK; kt++) {
        if (kt + 1 < nK) prefetch((kt + 1) << 5);

        const unsigned* Ah = smemu + (kt & 1) * BUF_U32;
        const unsigned* Al = Ah + 2560;
        const unsigned* Bh = Ah + 5120;
        const unsigned* Bl = Ah + 7296;

        #pragma unroll
        for (int kk = 0; kk < 2; kk++) {
            unsigned ah[2][4], al[2][4], bb[8][2];
            const int kc = kk * 8 + tg;
            #pragma unroll
            for (int mi = 0; mi < 2; mi++) {
                const int rb = wm + mi * 16 + gp;
                ah[mi][0] = Ah[rb * 20 + kc];
                ah[mi][1] = Ah[(rb + 8) * 20 + kc];
                ah[mi][2] = Ah[rb * 20 + kc + 4];
                ah[mi][3] = Ah[(rb + 8) * 20 + kc + 4];
                al[mi][0] = Al[rb * 20 + kc];
                al[mi][1] = Al[(rb + 8) * 20 + kc];
                al[mi][2] = Al[rb * 20 + kc + 4];
                al[mi][3] = Al[(rb + 8) * 20 + kc + 4];
            }
            #pragma unroll
            for (int ni = 0; ni < 8; ni++) {
                const int col = wn + ni * 8 + gp;
                bb[ni][0] = Bh[(kk * 8 + tg) * 136 + col];
                bb[ni][1] = Bh[(kk * 8 + 4 + tg) * 136 + col];
            }
            #pragma unroll
            for (int mi = 0; mi < 2; mi++)
                #pragma unroll
                for (int ni = 0; ni < 8; ni++) {
                    mma_bf16(c[mi][ni], ah[mi], bb[ni]);   // hi*hi
                    mma_bf16(c[mi][ni], al[mi], bb[ni]);   // lo*hi
                }
            #pragma unroll
            for (int ni = 0; ni < 8; ni++) {
                const int col = wn + ni * 8 + gp;
                bb[ni][0] = Bl[(kk * 8 + tg) * 136 + col];
                bb[ni][1] = Bl[(kk * 8 + 4 + tg) * 136 + col];
            }
            #pragma unroll
            for (int mi = 0; mi < 2; mi++)
                #pragma unroll
                for (int ni = 0; ni < 8; ni++)
                    mma_bf16(c[mi][ni], ah[mi], bb[ni]);   // hi*lo
        }

        if (kt + 1 < nK) store_buf((kt + 1) & 1);
        __syncthreads();
    }

    #pragma unroll
    for (int mi = 0; mi < 2; mi++)
        #pragma unroll
        for (int ni = 0; ni < 8; ni++) {
            const int col = n0 + wn + ni * 8 + tg * 2;
            const float b0 = bias[col], b1 = bias[col + 1];
            #pragma unroll
            for (int hh = 0; hh < 2; hh++) {
                const int row = m0 + wm + mi * 16 + gp + hh * 8;
                if (row < M) {
                    float v0 = c[mi][ni][hh * 2 + 0] + b0;
                    float v1 = c[mi][ni][hh * 2 + 1] + b1;
                    if (OP == 1) {
                        v0 = gelu_exact(v0); v1 = gelu_exact(v1);
                        __nv_bfloat16 h0 = __float2bfloat16(v0);
                        __nv_bfloat16 h1 = __float2bfloat16(v1);
                        *(__nv_bfloat162*)(Oh + (size_t)row * N + col) = __nv_bfloat162{h0, h1};
                        *(__nv_bfloat162*)(Ol + (size_t)row * N + col) = __nv_bfloat162{
                            __float2bfloat16(v0 - __bfloat162float(h0)),
                            __float2bfloat16(v1 - __bfloat162float(h1))};
                    } else {
                        if (OP == 2) {
                            float2 rr = *(const float2*)(res + (size_t)row * N + col);
                            v0 += rr.x; v1 += rr.y;
                        }
                        *(float2*)(Cout + (size_t)row * N + col) = make_float2(v0, v1);
                    }
                }
            }
        }
}

// ---------------------------------------------------------------------------
// 5) Fused attention, 4-row register blocking per warp (R7 layout).
//    Writes split bf16 output to g_atth / g_attl.
// ---------------------------------------------------------------------------
constexpr int ATTN_SMEM = 44704 * 4;   // 178816 B

__global__ __launch_bounds__(256) void attn_kernel() {
    extern __shared__ float sm[];
    float* Ks = sm;                      // [257][65]
    float* Vs = sm + 16720;              // [257][65]
    float* Q4 = sm + 33440;              // [8 warps][64 k][4 rows]
    float* P4 = sm + 35488;              // [8 warps][288 j][4 rows]

    const int b = blockIdx.x / kNH, hh = blockIdx.x % kNH;
    const int tid = threadIdx.x, w = tid >> 5, lane = tid & 31;
    const float* base = g_qkv + (size_t)b * kN * kQKV + hh * kHD;

    for (int i = tid; i < kN * kHD; i += 256) {
        const int n = i >> 6, d = i & 63;
        Ks[n * 65 + d] = base[(size_t)n * kQKV + kD + d];
        Vs[n * 65 + d] = base[(size_t)n * kQKV + 2 * kD + d];
    }
    __syncthreads();

    float* Q4w = Q4 + w * 256;
    float* P4w = P4 + w * 1152;

    for (int pass = 0; pass < 9; pass++) {
        const int r0 = pass * 32 + w * 4;

        #pragma unroll
        for (int hk = 0; hk < 2; hk++) {
            const int k = hk * 32 + lane;
            #pragma unroll
            for (int rr = 0; rr < 4; rr++) {
                int r = r0 + rr; if (r >= kN) r = kN - 1;
                Q4w[k * 4 + rr] = base[(size_t)r * kQKV + k];
            }
        }
        __syncwarp();

        float s[4][9];
        #pragma unroll
        for (int t = 0; t < 9; t++) {
            const int j = t * 32 + lane;
            const int jj = (j < kN) ? j : 0;
            const float* kr = Ks + jj * 65;
            float a0 = 0.f, a1 = 0.f, a2 = 0.f, a3 = 0.f;
            #pragma unroll 16
            for (int k = 0; k < 64; k++) {
                const float kv = kr[k];
                const float4 qv = *(const float4*)(Q4w + k * 4);
                a0 += qv.x * kv; a1 += qv.y * kv;
                a2 += qv.z * kv; a3 += qv.w * kv;
            }
            const float ninf = -__int_as_float(0x7f800000);
            s[0][t] = (j < kN) ? a0 * 0.125f : ninf;
            s[1][t] = (j < kN) ? a1 * 0.125f : ninf;
            s[2][t] = (j < kN) ? a2 * 0.125f : ninf;
            s[3][t] = (j < kN) ? a3 * 0.125f : ninf;
        }

        #pragma unroll
        for (int rr = 0; rr < 4; rr++) {
            float mx = s[rr][0];
            #pragma unroll
            for (int t = 1; t < 9; t++) mx = fmaxf(mx, s[rr][t]);
            #pragma unroll
            for (int o = 16; o > 0; o >>= 1) mx = fmaxf(mx, __shfl_xor_sync(0xffffffffu, mx, o));
            float sum = 0.f;
            #pragma unroll
            for (int t = 0; t < 9; t++) { s[rr][t] = __expf(s[rr][t] - mx); sum += s[rr][t]; }
            #pragma unroll
            for (int o = 16; o > 0; o >>= 1) sum += __shfl_xor_sync(0xffffffffu, sum, o);
            const float inv = 1.0f / sum;
            #pragma unroll
            for (int t = 0; t < 9; t++) P4w[(t * 32 + lane) * 4 + rr] = s[rr][t] * inv;
        }
        __syncwarp();

        float o0[4] = {0.f, 0.f, 0.f, 0.f};
        float o1[4] = {0.f, 0.f, 0.f, 0.f};
        #pragma unroll 4
        for (int j = 0; j < kN; j++) {
            const float v0 = Vs[j * 65 + lane];
            const float v1 = Vs[j * 65 + 32 + lane];
            const float4 p = *(const float4*)(P4w + j * 4);
            o0[0] += p.x * v0; o1[0] += p.x * v1;
            o0[1] += p.y * v0; o1[1] += p.y * v1;
            o0[2] += p.z * v0; o1[2] += p.z * v1;
            o0[3] += p.w * v0; o1[3] += p.w * v1;
        }

        #pragma unroll
        for (int rr = 0; rr < 4; rr++) {
            const int r = r0 + rr;
            if (r < kN) {
                const size_t idx = (size_t)(b * kN + r) * kD + hh * kHD;
                __nv_bfloat16 h0 = __float2bfloat16(o0[rr]);
                __nv_bfloat16 h1 = __float2bfloat16(o1[rr]);
                g_atth[idx + lane]      = h0;
                g_atth[idx + lane + 32] = h1;
                g_attl[idx + lane]      = __float2bfloat16(o0[rr] - __bfloat162float(h0));
                g_attl[idx + lane + 32] = __float2bfloat16(o1[rr] - __bfloat162float(h1));
            }
        }
        __syncwarp();
    }
}

// ---------------------------------------------------------------------------
// 6) Head
// ---------------------------------------------------------------------------
__global__ void head_kernel(const float* __restrict__ hw, const float* __restrict__ hb,
                            float* __restrict__ out) {
    __shared__ float xs[kD];
    const int b = blockIdx.y;
    const int col = blockIdx.x * 256 + threadIdx.x;
    for (int i = threadIdx.x; i < kD; i += 256) xs[i] = g_cls[b * kD + i];
    __syncthreads();
    if (col < kNC) {
        float acc = hb[col];
        #pragma unroll 4
        for (int k = 0; k < kD; k++) acc += xs[k] * hw[(size_t)k * kNC + col];
        out[(size_t)b * kNC + col] = acc;
    }
}

// ---------------------------------------------------------------------------
// Launch
// ---------------------------------------------------------------------------
extern "C" void kernel_launch(void* const* d_in, const int* in_sizes, int n_in,
                              void* d_out, int out_size) {
    const float* img    = (const float*)d_in[0];
    const int*   seg    = (const int*)  d_in[1];
    const float* w_fe   = (const float*)d_in[2];
    const float* b_fe   = (const float*)d_in[3];
    const float* cls_t  = (const float*)d_in[4];
    const float* pos    = (const float*)d_in[5];
    const float* ln1_g  = (const float*)d_in[6];
    const float* ln1_b  = (const float*)d_in[7];
    const float* qkv_w  = (const float*)d_in[8];
    const float* qkv_b  = (const float*)d_in[9];
    const float* proj_w = (const float*)d_in[10];
    const float* proj_b = (const float*)d_in[11];
    const float* ln2_g  = (const float*)d_in[12];
    const float* ln2_b  = (const float*)d_in[13];
    const float* mlp_w1 = (const float*)d_in[14];
    const float* mlp_b1 = (const float*)d_in[15];
    const float* mlp_w2 = (const float*)d_in[16];
    const float* mlp_b2 = (const float*)d_in[17];
    const float* norm_g = (const float*)d_in[18];
    const float* norm_b = (const float*)d_in[19];
    const float* head_w = (const float*)d_in[20];
    const float* head_b = (const float*)d_in[21];

    cudaFuncSetAttribute(attn_kernel,    cudaFuncAttributeMaxDynamicSharedMemorySize, ATTN_SMEM);
    cudaFuncSetAttribute(gemm_kernel<0>, cudaFuncAttributeMaxDynamicSharedMemorySize, GEMM_SMEM);
    cudaFuncSetAttribute(gemm_kernel<1>, cudaFuncAttributeMaxDynamicSharedMemorySize, GEMM_SMEM);
    cudaFuncSetAttribute(gemm_kernel<2>, cudaFuncAttributeMaxDynamicSharedMemorySize, GEMM_SMEM);

    float *px, *pq, *pc;
    cudaGetSymbolAddress((void**)&px, g_x);
    cudaGetSymbolAddress((void**)&pq, g_qkv);
    cudaGetSymbolAddress((void**)&pc, g_cls);

    __nv_bfloat16 *pah, *pal, *path, *patl, *pmh, *pml;
    __nv_bfloat16 *pwqh, *pwql, *pwph, *pwpl, *pw1h, *pw1l, *pw2h, *pw2l;
    cudaGetSymbolAddress((void**)&pah,  g_ah);
    cudaGetSymbolAddress((void**)&pal,  g_al);
    cudaGetSymbolAddress((void**)&path, g_atth);
    cudaGetSymbolAddress((void**)&patl, g_attl);
    cudaGetSymbolAddress((void**)&pmh,  g_mlph);
    cudaGetSymbolAddress((void**)&pml,  g_mlpl);
    cudaGetSymbolAddress((void**)&pwqh, g_wqkvh);
    cudaGetSymbolAddress((void**)&pwql, g_wqkvl);
    cudaGetSymbolAddress((void**)&pwph, g_wprojh);
    cudaGetSymbolAddress((void**)&pwpl, g_wprojl);
    cudaGetSymbolAddress((void**)&pw1h, g_wm1h);
    cudaGetSymbolAddress((void**)&pw1l, g_wm1l);
    cudaGetSymbolAddress((void**)&pw2h, g_wm2h);
    cudaGetSymbolAddress((void**)&pw2l, g_wm2l);

    // weight pre-split (once per call)
    const int nq = kL * kD * kQKV / 4, np = kL * kD * kD / 4;
    const int n1 = kL * kD * kMLP / 4, n2 = kL * kMLP * kD / 4;
    wsplit_kernel<<<(nq + 255) / 256, 256>>>(qkv_w,  pwqh, pwql, nq);
    wsplit_kernel<<<(np + 255) / 256, 256>>>(proj_w, pwph, pwpl, np);
    wsplit_kernel<<<(n1 + 255) / 256, 256>>>(mlp_w1, pw1h, pw1l, n1);
    wsplit_kernel<<<(n2 + 255) / 256, 256>>>(mlp_w2, pw2h, pw2l, n2);

    seg_sum_kernel<<<kB, 256>>>(img, seg);
    embed_kernel<<<kM, 256>>>(w_fe, b_fe, cls_t, pos);

    const dim3 gQKV(kQKV / 128, (kM + 127) / 128);
    const dim3 gD  (kD   / 128, (kM + 127) / 128);
    const dim3 gMLP(kMLP / 128, (kM + 127) / 128);

    for (int l = 0; l < kL; l++) {
        ln_kernel<true><<<kM, 256>>>(px, nullptr, pah, pal,
                                     ln1_g + (size_t)l * kD, ln1_b + (size_t)l * kD, kD);
        gemm_kernel<0><<<gQKV, 256, GEMM_SMEM>>>(
            pah, pal, pwqh + (size_t)l * kD * kQKV, pwql + (size_t)l * kD * kQKV,
            qkv_b + (size_t)l * kQKV, nullptr, pq, nullptr, nullptr, kM, kQKV, kD);
        attn_kernel<<<kB * kNH, 256, ATTN_SMEM>>>();
        gemm_kernel<2><<<gD, 256, GEMM_SMEM>>>(
            path, patl, pwph + (size_t)l * kD * kD, pwpl + (size_t)l * kD * kD,
            proj_b + (size_t)l * kD, px, px, nullptr, nullptr, kM, kD, kD);
        ln_kernel<true><<<kM, 256>>>(px, nullptr, pah, pal,
                                     ln2_g + (size_t)l * kD, ln2_b + (size_t)l * kD, kD);
        gemm_kernel<1><<<gMLP, 256, GEMM_SMEM>>>(
            pah, pal, pw1h + (size_t)l * kD * kMLP, pw1l + (size_t)l * kD * kMLP,
            mlp_b1 + (size_t)l * kMLP, nullptr, nullptr, pmh, pml, kM, kMLP, kD);
        gemm_kernel<2><<<gD, 256, GEMM_SMEM>>>(
            pmh, pml, pw2h + (size_t)l * kMLP * kD, pw2l + (size_t)l * kMLP * kD,
            mlp_b2 + (size_t)l * kD, px, px, nullptr, nullptr, kM, kD, kMLP);
    }

    // Final LN on cls rows only (row b at x + b*257*768), fp32 out, then head.
    ln_kernel<false><<<kB, 256>>>(px, pc, nullptr, nullptr, norm_g, norm_b, (long)kN * kD);
    head_kernel<<<dim3((kNC + 255) / 256, kB), 256>>>(head_w, head_b, (float*)d_out);
}

// round 16
// speedup vs baseline: 1.1022x; 1.1022x over previous
#include <cuda_runtime.h>
#include <cuda_bf16.h>
#include <math.h>

// ---------------------------------------------------------------------------
// Problem constants
// ---------------------------------------------------------------------------
constexpr int kB  = 32, kC = 3, kH = 224, kW = 224;
constexpr int kHW = kH * kW;          // 50176
constexpr int kS  = 256, kD = 768, kL = 12, kNH = 12, kHD = 64;
constexpr int kMLP = 3072, kNC = 1000;
constexpr int kN  = kS + 1;           // 257 tokens
constexpr int kM  = kB * kN;          // 8224 rows
constexpr int kQKV = 3 * kD;          // 2304

// ---------------------------------------------------------------------------
// Scratch (static device globals -- allowed; runtime allocation is not)
// ---------------------------------------------------------------------------
__device__ float g_x[kM * kD];
__device__ float g_h[kM * kD];
__device__ float g_qkv[kM * kQKV];
__device__ float g_att[kM * kD];
__device__ float g_mlp[kM * kMLP];
__device__ float g_seg[kB * kS * kC];
__device__ float g_cls[kB * kD];

// ---------------------------------------------------------------------------
// Helpers
// ---------------------------------------------------------------------------
__device__ __forceinline__ float gelu_exact(float x) {
    return 0.5f * x * (1.0f + erff(x * 0.70710678118654752440f));
}

__device__ __forceinline__ unsigned packbf(float a, float b) {
    __nv_bfloat162 t = __floats2bfloat162_rn(a, b);
    return *reinterpret_cast<unsigned*>(&t);
}

// bf16 m16n8k16 MMA, fp32 accumulate
__device__ __forceinline__ void mma_bf16(float c[4], const unsigned a[4], const unsigned b[2]) {
    asm volatile(
        "mma.sync.aligned.m16n8k16.row.col.f32.bf16.bf16.f32 "
        "{%0,%1,%2,%3}, {%4,%5,%6,%7}, {%8,%9}, {%0,%1,%2,%3};\n"
        : "+f"(c[0]), "+f"(c[1]), "+f"(c[2]), "+f"(c[3])
        : "r"(a[0]), "r"(a[1]), "r"(a[2]), "r"(a[3]), "r"(b[0]), "r"(b[1]));
}

// ---------------------------------------------------------------------------
// 1) Superpixel segment sums: one block per batch image, smem histogram
// ---------------------------------------------------------------------------
__global__ void seg_sum_kernel(const float* __restrict__ img, const int* __restrict__ seg) {
    __shared__ float sm[kS * kC];
    const int b = blockIdx.x;
    for (int i = threadIdx.x; i < kS * kC; i += blockDim.x) sm[i] = 0.f;
    __syncthreads();
    const int*   sb = seg + (size_t)b * kHW;
    const float* i0 = img + (size_t)(b * kC + 0) * kHW;
    const float* i1 = img + (size_t)(b * kC + 1) * kHW;
    const float* i2 = img + (size_t)(b * kC + 2) * kHW;
    for (int p = threadIdx.x; p < kHW; p += blockDim.x) {
        int s = sb[p];
        atomicAdd(&sm[s * 3 + 0], i0[p]);
        atomicAdd(&sm[s * 3 + 1], i1[p]);
        atomicAdd(&sm[s * 3 + 2], i2[p]);
    }
    __syncthreads();
    for (int i = threadIdx.x; i < kS * kC; i += blockDim.x) g_seg[b * kS * kC + i] = sm[i];
}

// ---------------------------------------------------------------------------
// 2) Build x = concat(cls, seg_mean @ w_fe + b_fe) + pos_embed
// ---------------------------------------------------------------------------
__global__ void embed_kernel(const float* __restrict__ w_fe, const float* __restrict__ b_fe,
                             const float* __restrict__ cls_t, const float* __restrict__ pos) {
    const int tok = blockIdx.x;
    const int b = tok / kN, n = tok % kN;
    float s0 = 0.f, s1 = 0.f, s2 = 0.f;
    if (n > 0) {
        const float* sp = g_seg + (size_t)(b * kS + (n - 1)) * 3;
        const float inv = 1.0f / (float)kHW;
        s0 = sp[0] * inv; s1 = sp[1] * inv; s2 = sp[2] * inv;
    }
    float* xr = g_x + (size_t)tok * kD;
    for (int d = threadIdx.x; d < kD; d += blockDim.x) {
        float pv = pos[n * kD + d];
        float v;
        if (n == 0) v = cls_t[d] + pv;
        else        v = b_fe[d] + pv + s0 * w_fe[d] + s1 * w_fe[kD + d] + s2 * w_fe[2 * kD + d];
        xr[d] = v;
    }
}

// ---------------------------------------------------------------------------
// 3) LayerNorm (one block per row, D=768, 256 threads x 3 elems)
// ---------------------------------------------------------------------------
__global__ __launch_bounds__(256) void ln_kernel(const float* __restrict__ x, float* __restrict__ y,
                          const float* __restrict__ gw, const float* __restrict__ bw,
                          long xstride, long ystride) {
    const int row = blockIdx.x;
    const float* xr = x + (long)row * xstride;
    float*       yr = y + (long)row * ystride;
    const int tid = threadIdx.x;
    float v0 = xr[tid], v1 = xr[tid + 256], v2 = xr[tid + 512];
    __shared__ float red[8];

    float s = v0 + v1 + v2;
    #pragma unroll
    for (int o = 16; o > 0; o >>= 1) s += __shfl_down_sync(0xffffffffu, s, o);
    if ((tid & 31) == 0) red[tid >> 5] = s;
    __syncthreads();
    if (tid < 8) {
        float t = red[tid];
        #pragma unroll
        for (int o = 4; o > 0; o >>= 1) t += __shfl_down_sync(0xffu, t, o);
        if (tid == 0) red[0] = t;
    }
    __syncthreads();
    const float m = red[0] * (1.0f / kD);
    __syncthreads();

    const float d0 = v0 - m, d1 = v1 - m, d2 = v2 - m;
    float q = d0 * d0 + d1 * d1 + d2 * d2;
    #pragma unroll
    for (int o = 16; o > 0; o >>= 1) q += __shfl_down_sync(0xffffffffu, q, o);
    if ((tid & 31) == 0) red[tid >> 5] = q;
    __syncthreads();
    if (tid < 8) {
        float t = red[tid];
        #pragma unroll
        for (int o = 4; o > 0; o >>= 1) t += __shfl_down_sync(0xffu, t, o);
        if (tid == 0) red[0] = t;
    }
    __syncthreads();
    const float inv = rsqrtf(red[0] * (1.0f / kD) + 1e-6f);

    yr[tid]       = d0 * inv * gw[tid]       + bw[tid];
    yr[tid + 256] = d1 * inv * gw[tid + 256] + bw[tid + 256];
    yr[tid + 512] = d2 * inv * gw[tid + 512] + bw[tid + 512];
}

// ---------------------------------------------------------------------------
// 4) Split-bf16 GEMM (R7 exact): C = epilogue(A[M,K] @ W[K,N] + bias)
//    BM=BN=128, BK=32, 256 threads, warp tile 32x64, m16n8k16 hi/lo 3-term.
//    Double-buffered smem + register prefetch. 2 CTAs/SM.
// ---------------------------------------------------------------------------
constexpr int BUF_U32   = 9472;
constexpr int GEMM_SMEM = 2 * BUF_U32 * 4;   // 75776 B

template <int OP>   // 0: +bias   1: +bias, gelu   2: +bias, +res
__global__ __launch_bounds__(256, 2) void gemm_kernel(
    const float* __restrict__ A, const float* __restrict__ Wm,
    const float* __restrict__ bias, const float* __restrict__ res,
    float* __restrict__ Cout, int M, int N, int K)
{
    extern __shared__ unsigned smemu[];

    const int tid = threadIdx.x;
    const int wid = tid >> 5, lane = tid & 31;
    const int gp = lane >> 2, tg = lane & 3;
    const int wm = (wid >> 1) * 32;     // 4 warps along M
    const int wn = (wid & 1) * 64;      // 2 warps along N
    const int m0 = blockIdx.y * 128;
    const int n0 = blockIdx.x * 128;

    float c[2][8][4];
    #pragma unroll
    for (int i = 0; i < 2; i++)
        #pragma unroll
        for (int j = 0; j < 8; j++)
            #pragma unroll
            for (int r = 0; r < 4; r++) c[i][j][r] = 0.f;

    // loader indices
    const int arow = tid >> 3, ac4 = tid & 7;      // A: 4 rows-of-32, float4 col
    const int bq   = tid >> 5, bc4 = tid & 31;     // B: 2 q-groups of 8, float4 col

    float4 apf[4];
    float4 bpf[2][2];

    const int nK = K >> 5;

    auto prefetch = [&](int k0) {
        #pragma unroll
        for (int p = 0; p < 4; p++) {
            const int grow = m0 + p * 32 + arow;
            if (grow < M) apf[p] = *(const float4*)(A + (size_t)grow * K + k0 + ac4 * 4);
            else          apf[p] = make_float4(0.f, 0.f, 0.f, 0.f);
        }
        #pragma unroll
        for (int p = 0; p < 2; p++) {
            const int q = p * 8 + bq;
            const float* bp = Wm + (size_t)(k0 + 2 * q) * N + n0 + bc4 * 4;
            bpf[p][0] = *(const float4*)bp;
            bpf[p][1] = *(const float4*)(bp + N);
        }
    };

    auto store_buf = [&](int buf) {
        unsigned* Ah = smemu + buf * BUF_U32;
        unsigned* Al = Ah + 2560;
        unsigned* Bh = Ah + 5120;
        unsigned* Bl = Ah + 7296;
        #pragma unroll
        for (int p = 0; p < 4; p++) {
            const int r = p * 32 + arow;
            float v[4] = {apf[p].x, apf[p].y, apf[p].z, apf[p].w};
            float hf[4], lf[4];
            #pragma unroll
            for (int i = 0; i < 4; i++) {
                hf[i] = __bfloat162float(__float2bfloat16(v[i]));
                lf[i] = v[i] - hf[i];
            }
            Ah[r * 20 + ac4 * 2]     = packbf(hf[0], hf[1]);
            Ah[r * 20 + ac4 * 2 + 1] = packbf(hf[2], hf[3]);
            Al[r * 20 + ac4 * 2]     = packbf(lf[0], lf[1]);
            Al[r * 20 + ac4 * 2 + 1] = packbf(lf[2], lf[3]);
        }
        #pragma unroll
        for (int p = 0; p < 2; p++) {
            const int q = p * 8 + bq;
            float v0[4] = {bpf[p][0].x, bpf[p][0].y, bpf[p][0].z, bpf[p][0].w};
            float v1[4] = {bpf[p][1].x, bpf[p][1].y, bpf[p][1].z, bpf[p][1].w};
            #pragma unroll
            for (int i = 0; i < 4; i++) {
                float h0 = __bfloat162float(__float2bfloat16(v0[i]));
                float h1 = __bfloat162float(__float2bfloat16(v1[i]));
                Bh[q * 136 + bc4 * 4 + i] = packbf(h0, h1);
                Bl[q * 136 + bc4 * 4 + i] = packbf(v0[i] - h0, v1[i] - h1);
            }
        }
    };

    prefetch(0);
    store_buf(0);
    __syncthreads();

    for (int kt = 0; kt < nK; kt++) {
        if (kt + 1 < nK) prefetch((kt + 1) << 5);

        const unsigned* Ah = smemu + (kt & 1) * BUF_U32;
        const unsigned* Al = Ah + 2560;
        const unsigned* Bh = Ah + 5120;
        const unsigned* Bl = Ah + 7296;

        #pragma unroll
        for (int kk = 0; kk < 2; kk++) {
            unsigned ah[2][4], al[2][4], bb[8][2];
            const int kc = kk * 8 + tg;
            #pragma unroll
            for (int mi = 0; mi < 2; mi++) {
                const int rb = wm + mi * 16 + gp;
                ah[mi][0] = Ah[rb * 20 + kc];
                ah[mi][1] = Ah[(rb + 8) * 20 + kc];
                ah[mi][2] = Ah[rb * 20 + kc + 4];
                ah[mi][3] = Ah[(rb + 8) * 20 + kc + 4];
                al[mi][0] = Al[rb * 20 + kc];
                al[mi][1] = Al[(rb + 8) * 20 + kc];
                al[mi][2] = Al[rb * 20 + kc + 4];
                al[mi][3] = Al[(rb + 8) * 20 + kc + 4];
            }
            #pragma unroll
            for (int ni = 0; ni < 8; ni++) {
                const int col = wn + ni * 8 + gp;
                bb[ni][0] = Bh[(kk * 8 + tg) * 136 + col];
                bb[ni][1] = Bh[(kk * 8 + 4 + tg) * 136 + col];
            }
            #pragma unroll
            for (int mi = 0; mi < 2; mi++)
                #pragma unroll
                for (int ni = 0; ni < 8; ni++) {
                    mma_bf16(c[mi][ni], ah[mi], bb[ni]);   // hi*hi
                    mma_bf16(c[mi][ni], al[mi], bb[ni]);   // lo*hi
                }
            #pragma unroll
            for (int ni = 0; ni < 8; ni++) {
                const int col = wn + ni * 8 + gp;
                bb[ni][0] = Bl[(kk * 8 + tg) * 136 + col];
                bb[ni][1] = Bl[(kk * 8 + 4 + tg) * 136 + col];
            }
            #pragma unroll
            for (int mi = 0; mi < 2; mi++)
                #pragma unroll
                for (int ni = 0; ni < 8; ni++)
                    mma_bf16(c[mi][ni], ah[mi], bb[ni]);   // hi*lo
        }

        if (kt + 1 < nK) store_buf((kt + 1) & 1);
        __syncthreads();
    }

    #pragma unroll
    for (int mi = 0; mi < 2; mi++)
        #pragma unroll
        for (int ni = 0; ni < 8; ni++) {
            const int col = n0 + wn + ni * 8 + tg * 2;
            const float b0 = bias[col], b1 = bias[col + 1];
            #pragma unroll
            for (int hh = 0; hh < 2; hh++) {
                const int row = m0 + wm + mi * 16 + gp + hh * 8;
                if (row < M) {
                    float v0 = c[mi][ni][hh * 2 + 0] + b0;
                    float v1 = c[mi][ni][hh * 2 + 1] + b1;
                    if (OP == 1) { v0 = gelu_exact(v0); v1 = gelu_exact(v1); }
                    if (OP == 2) {
                        float2 rr = *(const float2*)(res + (size_t)row * N + col);
                        v0 += rr.x; v1 += rr.y;
                    }
                    *(float2*)(Cout + (size_t)row * N + col) = make_float2(v0, v1);
                }
            }
        }
}

// ---------------------------------------------------------------------------
// 5) Fused attention, 4-row blocking, 512 threads (16 warps = 4/SMSP for
//    latency hiding).  64 rows per pass, 5 passes.
//    smem floats: Ks[257][65] pad->16720 | Vs +16720 -> 33440 |
//                 Q4 @33440 (16x256=4096) | P4 @37536 (16x1152=18432)
//                 total 55968 floats = 223872 B (< 227KB cap).
// ---------------------------------------------------------------------------
constexpr int ATTN_SMEM = 55968 * 4;   // 223872 B

__global__ __launch_bounds__(512) void attn_kernel() {
    extern __shared__ float sm[];
    float* Ks = sm;                      // [257][65]
    float* Vs = sm + 16720;              // [257][65]
    float* Q4 = sm + 33440;              // [16 warps][64 k][4 rows]
    float* P4 = sm + 37536;              // [16 warps][288 j][4 rows]

    const int b = blockIdx.x / kNH, hh = blockIdx.x % kNH;
    const int tid = threadIdx.x, w = tid >> 5, lane = tid & 31;
    const float* base = g_qkv + (size_t)b * kN * kQKV + hh * kHD;

    for (int i = tid; i < kN * kHD; i += 512) {
        const int n = i >> 6, d = i & 63;
        Ks[n * 65 + d] = base[(size_t)n * kQKV + kD + d];
        Vs[n * 65 + d] = base[(size_t)n * kQKV + 2 * kD + d];
    }
    __syncthreads();

    float* Q4w = Q4 + w * 256;
    float* P4w = P4 + w * 1152;

    for (int pass = 0; pass < 5; pass++) {
        const int r0 = pass * 64 + w * 4;

        // stage Q for 4 rows (clamped; extra rows never stored)
        #pragma unroll
        for (int hk = 0; hk < 2; hk++) {
            const int k = hk * 32 + lane;
            #pragma unroll
            for (int rr = 0; rr < 4; rr++) {
                int r = r0 + rr; if (r >= kN) r = kN - 1;
                Q4w[k * 4 + rr] = base[(size_t)r * kQKV + k];
            }
        }
        __syncwarp();

        // scores: lane owns j = t*32+lane, 4 rows at once
        float s[4][9];
        #pragma unroll
        for (int t = 0; t < 9; t++) {
            const int j = t * 32 + lane;
            const int jj = (j < kN) ? j : 0;
            const float* kr = Ks + jj * 65;
            float a0 = 0.f, a1 = 0.f, a2 = 0.f, a3 = 0.f;
            #pragma unroll 16
            for (int k = 0; k < 64; k++) {
                const float kv = kr[k];
                const float4 qv = *(const float4*)(Q4w + k * 4);
                a0 += qv.x * kv; a1 += qv.y * kv;
                a2 += qv.z * kv; a3 += qv.w * kv;
            }
            const float ninf = -__int_as_float(0x7f800000);
            s[0][t] = (j < kN) ? a0 * 0.125f : ninf;
            s[1][t] = (j < kN) ? a1 * 0.125f : ninf;
            s[2][t] = (j < kN) ? a2 * 0.125f : ninf;
            s[3][t] = (j < kN) ? a3 * 0.125f : ninf;
        }

        // softmax per row; write probs as float4-per-j
        #pragma unroll
        for (int rr = 0; rr < 4; rr++) {
            float mx = s[rr][0];
            #pragma unroll
            for (int t = 1; t < 9; t++) mx = fmaxf(mx, s[rr][t]);
            #pragma unroll
            for (int o = 16; o > 0; o >>= 1) mx = fmaxf(mx, __shfl_xor_sync(0xffffffffu, mx, o));
            float sum = 0.f;
            #pragma unroll
            for (int t = 0; t < 9; t++) { s[rr][t] = __expf(s[rr][t] - mx); sum += s[rr][t]; }
            #pragma unroll
            for (int o = 16; o > 0; o >>= 1) sum += __shfl_xor_sync(0xffffffffu, sum, o);
            const float inv = 1.0f / sum;
            #pragma unroll
            for (int t = 0; t < 9; t++) P4w[(t * 32 + lane) * 4 + rr] = s[rr][t] * inv;
        }
        __syncwarp();

        // AV: lane owns dims (lane, lane+32); 4 rows at once
        float o0[4] = {0.f, 0.f, 0.f, 0.f};
        float o1[4] = {0.f, 0.f, 0.f, 0.f};
        #pragma unroll 4
        for (int j = 0; j < kN; j++) {
            const float v0 = Vs[j * 65 + lane];
            const float v1 = Vs[j * 65 + 32 + lane];
            const float4 p = *(const float4*)(P4w + j * 4);
            o0[0] += p.x * v0; o1[0] += p.x * v1;
            o0[1] += p.y * v0; o1[1] += p.y * v1;
            o0[2] += p.z * v0; o1[2] += p.z * v1;
            o0[3] += p.w * v0; o1[3] += p.w * v1;
        }

        #pragma unroll
        for (int rr = 0; rr < 4; rr++) {
            const int r = r0 + rr;
            if (r < kN) {
                float* orow = g_att + (size_t)(b * kN + r) * kD + hh * kHD;
                orow[lane]      = o0[rr];
                orow[lane + 32] = o1[rr];
            }
        }
        __syncwarp();
    }
}

// ---------------------------------------------------------------------------
// 6) Head: out[b, c] = cls_ln[b] . head_w[:, c] + head_b[c]
// ---------------------------------------------------------------------------
__global__ void head_kernel(const float* __restrict__ hw, const float* __restrict__ hb,
                            float* __restrict__ out) {
    __shared__ float xs[kD];
    const int b = blockIdx.y;
    const int col = blockIdx.x * 256 + threadIdx.x;
    for (int i = threadIdx.x; i < kD; i += 256) xs[i] = g_cls[b * kD + i];
    __syncthreads();
    if (col < kNC) {
        float acc = hb[col];
        #pragma unroll 4
        for (int k = 0; k < kD; k++) acc += xs[k] * hw[(size_t)k * kNC + col];
        out[(size_t)b * kNC + col] = acc;
    }
}

// ---------------------------------------------------------------------------
// Launch
// ---------------------------------------------------------------------------
extern "C" void kernel_launch(void* const* d_in, const int* in_sizes, int n_in,
                              void* d_out, int out_size) {
    const float* img    = (const float*)d_in[0];
    const int*   seg    = (const int*)  d_in[1];
    const float* w_fe   = (const float*)d_in[2];
    const float* b_fe   = (const float*)d_in[3];
    const float* cls_t  = (const float*)d_in[4];
    const float* pos    = (const float*)d_in[5];
    const float* ln1_g  = (const float*)d_in[6];
    const float* ln1_b  = (const float*)d_in[7];
    const float* qkv_w  = (const float*)d_in[8];
    const float* qkv_b  = (const float*)d_in[9];
    const float* proj_w = (const float*)d_in[10];
    const float* proj_b = (const float*)d_in[11];
    const float* ln2_g  = (const float*)d_in[12];
    const float* ln2_b  = (const float*)d_in[13];
    const float* mlp_w1 = (const float*)d_in[14];
    const float* mlp_b1 = (const float*)d_in[15];
    const float* mlp_w2 = (const float*)d_in[16];
    const float* mlp_b2 = (const float*)d_in[17];
    const float* norm_g = (const float*)d_in[18];
    const float* norm_b = (const float*)d_in[19];
    const float* head_w = (const float*)d_in[20];
    const float* head_b = (const float*)d_in[21];

    cudaFuncSetAttribute(attn_kernel,    cudaFuncAttributeMaxDynamicSharedMemorySize, ATTN_SMEM);
    cudaFuncSetAttribute(gemm_kernel<0>, cudaFuncAttributeMaxDynamicSharedMemorySize, GEMM_SMEM);
    cudaFuncSetAttribute(gemm_kernel<1>, cudaFuncAttributeMaxDynamicSharedMemorySize, GEMM_SMEM);
    cudaFuncSetAttribute(gemm_kernel<2>, cudaFuncAttributeMaxDynamicSharedMemorySize, GEMM_SMEM);

    float *px, *ph, *pq, *pa, *pm, *pc;
    cudaGetSymbolAddress((void**)&px, g_x);
    cudaGetSymbolAddress((void**)&ph, g_h);
    cudaGetSymbolAddress((void**)&pq, g_qkv);
    cudaGetSymbolAddress((void**)&pa, g_att);
    cudaGetSymbolAddress((void**)&pm, g_mlp);
    cudaGetSymbolAddress((void**)&pc, g_cls);

    seg_sum_kernel<<<kB, 256>>>(img, seg);
    embed_kernel<<<kM, 256>>>(w_fe, b_fe, cls_t, pos);

    const dim3 gQKV(kQKV / 128, (kM + 127) / 128);
    const dim3 gD  (kD   / 128, (kM + 127) / 128);
    const dim3 gMLP(kMLP / 128, (kM + 127) / 128);

    for (int l = 0; l < kL; l++) {
        ln_kernel<<<kM, 256>>>(px, ph, ln1_g + (size_t)l * kD, ln1_b + (size_t)l * kD, kD, kD);
        gemm_kernel<0><<<gQKV, 256, GEMM_SMEM>>>(ph, qkv_w + (size_t)l * kD * kQKV,
                                                 qkv_b + (size_t)l * kQKV, nullptr, pq,
                                                 kM, kQKV, kD);
        attn_kernel<<<kB * kNH, 512, ATTN_SMEM>>>();
        gemm_kernel<2><<<gD, 256, GEMM_SMEM>>>(pa, proj_w + (size_t)l * kD * kD,
                                               proj_b + (size_t)l * kD, px, px,
                                               kM, kD, kD);
        ln_kernel<<<kM, 256>>>(px, ph, ln2_g + (size_t)l * kD, ln2_b + (size_t)l * kD, kD, kD);
        gemm_kernel<1><<<gMLP, 256, GEMM_SMEM>>>(ph, mlp_w1 + (size_t)l * kD * kMLP,
                                                 mlp_b1 + (size_t)l * kMLP, nullptr, pm,
                                                 kM, kMLP, kD);
        gemm_kernel<2><<<gD, 256, GEMM_SMEM>>>(pm, mlp_w2 + (size_t)l * kMLP * kD,
                                               mlp_b2 + (size_t)l * kD, px, px,
                                               kM, kD, kMLP);
    }

    // Final LN on cls rows only (row b lives at x + b*257*768), then head.
    ln_kernel<<<kB, 256>>>(px, pc, norm_g, norm_b, (long)kN * kD, (long)kD);
    head_kernel<<<dim3((kNC + 255) / 256, kB), 256>>>(head_w, head_b, (float*)d_out);
}

// round 17
// speedup vs baseline: 1.2720x; 1.1541x over previous
#include <cuda_runtime.h>
#include <cuda_bf16.h>
#include <math.h>

// ---------------------------------------------------------------------------
// Problem constants
// ---------------------------------------------------------------------------
constexpr int kB  = 32, kC = 3, kH = 224, kW = 224;
constexpr int kHW = kH * kW;          // 50176
constexpr int kS  = 256, kD = 768, kL = 12, kNH = 12, kHD = 64;
constexpr int kMLP = 3072, kNC = 1000;
constexpr int kN  = kS + 1;           // 257 tokens
constexpr int kM  = kB * kN;          // 8224 rows
constexpr int kQKV = 3 * kD;          // 2304

// ---------------------------------------------------------------------------
// Scratch (static device globals -- allowed; runtime allocation is not)
// ---------------------------------------------------------------------------
__device__ float g_x[kM * kD];
__device__ float g_h[kM * kD];
__device__ float g_qkv[kM * kQKV];
__device__ float g_att[kM * kD];
__device__ float g_mlp[kM * kMLP];
__device__ float g_seg[kB * kS * kC];
__device__ float g_cls[kB * kD];

// ---------------------------------------------------------------------------
// Helpers
// ---------------------------------------------------------------------------
__device__ __forceinline__ float gelu_exact(float x) {
    return 0.5f * x * (1.0f + erff(x * 0.70710678118654752440f));
}

__device__ __forceinline__ unsigned packbf(float a, float b) {
    __nv_bfloat162 t = __floats2bfloat162_rn(a, b);
    return *reinterpret_cast<unsigned*>(&t);
}

// bf16 m16n8k16 MMA, fp32 accumulate
__device__ __forceinline__ void mma_bf16(float c[4], const unsigned a[4], const unsigned b[2]) {
    asm volatile(
        "mma.sync.aligned.m16n8k16.row.col.f32.bf16.bf16.f32 "
        "{%0,%1,%2,%3}, {%4,%5,%6,%7}, {%8,%9}, {%0,%1,%2,%3};\n"
        : "+f"(c[0]), "+f"(c[1]), "+f"(c[2]), "+f"(c[3])
        : "r"(a[0]), "r"(a[1]), "r"(a[2]), "r"(a[3]), "r"(b[0]), "r"(b[1]));
}

__device__ __forceinline__ void mbar_init(unsigned addr, unsigned count) {
    asm volatile("mbarrier.init.shared.b64 [%0], %1;" :: "r"(addr), "r"(count) : "memory");
}
__device__ __forceinline__ void mbar_arrive(unsigned addr) {
    asm volatile("mbarrier.arrive.shared.b64 _, [%0];" :: "r"(addr) : "memory");
}
__device__ __forceinline__ void mbar_wait(unsigned mbar, unsigned parity) {
    asm volatile(
        "{\n\t.reg .pred P;\n\t"
        "W_%=:\n\t"
        "mbarrier.try_wait.parity.acquire.cta.shared::cta.b64 P, [%0], %1, 0x989680;\n\t"
        "@!P bra.uni W_%=;\n\t"
        "}"
        :: "r"(mbar), "r"(parity) : "memory");
}

// ---------------------------------------------------------------------------
// 1) Superpixel segment sums
// ---------------------------------------------------------------------------
__global__ void seg_sum_kernel(const float* __restrict__ img, const int* __restrict__ seg) {
    __shared__ float sm[kS * kC];
    const int b = blockIdx.x;
    for (int i = threadIdx.x; i < kS * kC; i += blockDim.x) sm[i] = 0.f;
    __syncthreads();
    const int*   sb = seg + (size_t)b * kHW;
    const float* i0 = img + (size_t)(b * kC + 0) * kHW;
    const float* i1 = img + (size_t)(b * kC + 1) * kHW;
    const float* i2 = img + (size_t)(b * kC + 2) * kHW;
    for (int p = threadIdx.x; p < kHW; p += blockDim.x) {
        int s = sb[p];
        atomicAdd(&sm[s * 3 + 0], i0[p]);
        atomicAdd(&sm[s * 3 + 1], i1[p]);
        atomicAdd(&sm[s * 3 + 2], i2[p]);
    }
    __syncthreads();
    for (int i = threadIdx.x; i < kS * kC; i += blockDim.x) g_seg[b * kS * kC + i] = sm[i];
}

// ---------------------------------------------------------------------------
// 2) Embedding build
// ---------------------------------------------------------------------------
__global__ void embed_kernel(const float* __restrict__ w_fe, const float* __restrict__ b_fe,
                             const float* __restrict__ cls_t, const float* __restrict__ pos) {
    const int tok = blockIdx.x;
    const int b = tok / kN, n = tok % kN;
    float s0 = 0.f, s1 = 0.f, s2 = 0.f;
    if (n > 0) {
        const float* sp = g_seg + (size_t)(b * kS + (n - 1)) * 3;
        const float inv = 1.0f / (float)kHW;
        s0 = sp[0] * inv; s1 = sp[1] * inv; s2 = sp[2] * inv;
    }
    float* xr = g_x + (size_t)tok * kD;
    for (int d = threadIdx.x; d < kD; d += blockDim.x) {
        float pv = pos[n * kD + d];
        float v;
        if (n == 0) v = cls_t[d] + pv;
        else        v = b_fe[d] + pv + s0 * w_fe[d] + s1 * w_fe[kD + d] + s2 * w_fe[2 * kD + d];
        xr[d] = v;
    }
}

// ---------------------------------------------------------------------------
// 3) LayerNorm
// ---------------------------------------------------------------------------
__global__ __launch_bounds__(256) void ln_kernel(const float* __restrict__ x, float* __restrict__ y,
                          const float* __restrict__ gw, const float* __restrict__ bw,
                          long xstride, long ystride) {
    const int row = blockIdx.x;
    const float* xr = x + (long)row * xstride;
    float*       yr = y + (long)row * ystride;
    const int tid = threadIdx.x;
    float v0 = xr[tid], v1 = xr[tid + 256], v2 = xr[tid + 512];
    __shared__ float red[8];

    float s = v0 + v1 + v2;
    #pragma unroll
    for (int o = 16; o > 0; o >>= 1) s += __shfl_down_sync(0xffffffffu, s, o);
    if ((tid & 31) == 0) red[tid >> 5] = s;
    __syncthreads();
    if (tid < 8) {
        float t = red[tid];
        #pragma unroll
        for (int o = 4; o > 0; o >>= 1) t += __shfl_down_sync(0xffu, t, o);
        if (tid == 0) red[0] = t;
    }
    __syncthreads();
    const float m = red[0] * (1.0f / kD);
    __syncthreads();

    const float d0 = v0 - m, d1 = v1 - m, d2 = v2 - m;
    float q = d0 * d0 + d1 * d1 + d2 * d2;
    #pragma unroll
    for (int o = 16; o > 0; o >>= 1) q += __shfl_down_sync(0xffffffffu, q, o);
    if ((tid & 31) == 0) red[tid >> 5] = q;
    __syncthreads();
    if (tid < 8) {
        float t = red[tid];
        #pragma unroll
        for (int o = 4; o > 0; o >>= 1) t += __shfl_down_sync(0xffu, t, o);
        if (tid == 0) red[0] = t;
    }
    __syncthreads();
    const float inv = rsqrtf(red[0] * (1.0f / kD) + 1e-6f);

    yr[tid]       = d0 * inv * gw[tid]       + bw[tid];
    yr[tid + 256] = d1 * inv * gw[tid + 256] + bw[tid + 256];
    yr[tid + 512] = d2 * inv * gw[tid + 512] + bw[tid + 512];
}

// ---------------------------------------------------------------------------
// 4) Warp-specialized split-bf16 GEMM.
//    384 threads: warps 0-7 consumers (fragment LDS + MMA + epilogue, exactly
//    the R16 math/layout), warps 8-11 producers (LDG fp32 -> hi/lo -> STS).
//    3-stage smem ring (stage = 9472 u32: Ah 2560 | Al 2560 | Bh 2176 | Bl
//    2176), mbarrier full/empty per stage, no __syncthreads in main loop.
// ---------------------------------------------------------------------------
constexpr int STG_U32   = 9472;
constexpr int GEMM_SMEM = 3 * STG_U32 * 4;   // 113664 B

template <int OP>   // 0: +bias   1: +bias, gelu   2: +bias, +res
__global__ __launch_bounds__(384, 1) void gemm_kernel(
    const float* __restrict__ A, const float* __restrict__ Wm,
    const float* __restrict__ bias, const float* __restrict__ res,
    float* __restrict__ Cout, int M, int N, int K)
{
    extern __shared__ unsigned smemu[];
    __shared__ unsigned long long bars[6];   // full[0..2], empty[3..5]

    const int tid = threadIdx.x;
    const int m0 = blockIdx.y * 128;
    const int n0 = blockIdx.x * 128;
    const int nK = K >> 5;

    const unsigned bar0 = (unsigned)__cvta_generic_to_shared(&bars[0]);

    if (tid == 0) {
        #pragma unroll
        for (int s = 0; s < 3; s++) {
            mbar_init(bar0 + s * 8, 128);        // full[s]: 128 producer arrivals
            mbar_init(bar0 + (3 + s) * 8, 256);  // empty[s]: 256 consumer arrivals
        }
    }
    __syncthreads();

    if (tid < 256) {
        // ------------------------- CONSUMER -------------------------
        const int wid = tid >> 5, lane = tid & 31;
        const int gp = lane >> 2, tg = lane & 3;
        const int wm = (wid >> 1) * 32;     // 4 warps along M
        const int wn = (wid & 1) * 64;      // 2 warps along N

        float c[2][8][4];
        #pragma unroll
        for (int i = 0; i < 2; i++)
            #pragma unroll
            for (int j = 0; j < 8; j++)
                #pragma unroll
                for (int r = 0; r < 4; r++) c[i][j][r] = 0.f;

        int stg = 0, par = 0;
        for (int kt = 0; kt < nK; kt++) {
            mbar_wait(bar0 + stg * 8, (unsigned)par);

            const unsigned* Ah = smemu + stg * STG_U32;
            const unsigned* Al = Ah + 2560;
            const unsigned* Bh = Ah + 5120;
            const unsigned* Bl = Ah + 7296;

            #pragma unroll
            for (int kk = 0; kk < 2; kk++) {
                unsigned ah[2][4], al[2][4], bb[8][2];
                const int kc = kk * 8 + tg;
                #pragma unroll
                for (int mi = 0; mi < 2; mi++) {
                    const int rb = wm + mi * 16 + gp;
                    ah[mi][0] = Ah[rb * 20 + kc];
                    ah[mi][1] = Ah[(rb + 8) * 20 + kc];
                    ah[mi][2] = Ah[rb * 20 + kc + 4];
                    ah[mi][3] = Ah[(rb + 8) * 20 + kc + 4];
                    al[mi][0] = Al[rb * 20 + kc];
                    al[mi][1] = Al[(rb + 8) * 20 + kc];
                    al[mi][2] = Al[rb * 20 + kc + 4];
                    al[mi][3] = Al[(rb + 8) * 20 + kc + 4];
                }
                #pragma unroll
                for (int ni = 0; ni < 8; ni++) {
                    const int col = wn + ni * 8 + gp;
                    bb[ni][0] = Bh[(kk * 8 + tg) * 136 + col];
                    bb[ni][1] = Bh[(kk * 8 + 4 + tg) * 136 + col];
                }
                #pragma unroll
                for (int mi = 0; mi < 2; mi++)
                    #pragma unroll
                    for (int ni = 0; ni < 8; ni++) {
                        mma_bf16(c[mi][ni], ah[mi], bb[ni]);   // hi*hi
                        mma_bf16(c[mi][ni], al[mi], bb[ni]);   // lo*hi
                    }
                #pragma unroll
                for (int ni = 0; ni < 8; ni++) {
                    const int col = wn + ni * 8 + gp;
                    bb[ni][0] = Bl[(kk * 8 + tg) * 136 + col];
                    bb[ni][1] = Bl[(kk * 8 + 4 + tg) * 136 + col];
                }
                #pragma unroll
                for (int mi = 0; mi < 2; mi++)
                    #pragma unroll
                    for (int ni = 0; ni < 8; ni++)
                        mma_bf16(c[mi][ni], ah[mi], bb[ni]);   // hi*lo
            }

            mbar_arrive(bar0 + (3 + stg) * 8);
            if (++stg == 3) { stg = 0; par ^= 1; }
        }

        // epilogue (unchanged)
        #pragma unroll
        for (int mi = 0; mi < 2; mi++)
            #pragma unroll
            for (int ni = 0; ni < 8; ni++) {
                const int col = n0 + wn + ni * 8 + tg * 2;
                const float b0 = bias[col], b1 = bias[col + 1];
                #pragma unroll
                for (int hh = 0; hh < 2; hh++) {
                    const int row = m0 + wm + mi * 16 + gp + hh * 8;
                    if (row < M) {
                        float v0 = c[mi][ni][hh * 2 + 0] + b0;
                        float v1 = c[mi][ni][hh * 2 + 1] + b1;
                        if (OP == 1) { v0 = gelu_exact(v0); v1 = gelu_exact(v1); }
                        if (OP == 2) {
                            float2 rr = *(const float2*)(res + (size_t)row * N + col);
                            v0 += rr.x; v1 += rr.y;
                        }
                        *(float2*)(Cout + (size_t)row * N + col) = make_float2(v0, v1);
                    }
                }
            }
    } else {
        // ------------------------- PRODUCER -------------------------
        const int ptid = tid - 256;                 // 0..127
        const int arow2 = ptid >> 2, acc = ptid & 3;   // A: 32 rows x 4 f4-cols
        const int bq2   = ptid >> 5, bc4 = ptid & 31;  // B: 4 q-groups, f4 col

        int stg = 0, par = 0;
        for (int kt = 0; kt < nK; kt++) {
            const int k0 = kt << 5;

            // issue all LDGs into registers BEFORE the empty-wait
            float4 av[4][2];
            #pragma unroll
            for (int p = 0; p < 4; p++) {
                const int grow = m0 + p * 32 + arow2;
                #pragma unroll
                for (int cix = 0; cix < 2; cix++) {
                    const int idx = acc + cix * 4;
                    if (grow < M)
                        av[p][cix] = *(const float4*)(A + (size_t)grow * K + k0 + idx * 4);
                    else
                        av[p][cix] = make_float4(0.f, 0.f, 0.f, 0.f);
                }
            }
            float4 bv[4][2];
            #pragma unroll
            for (int p = 0; p < 4; p++) {
                const int q = p * 4 + bq2;
                const float* bp = Wm + (size_t)(k0 + 2 * q) * N + n0 + bc4 * 4;
                bv[p][0] = *(const float4*)bp;
                bv[p][1] = *(const float4*)(bp + N);
            }

            if (kt >= 3) mbar_wait(bar0 + (3 + stg) * 8, (unsigned)(par ^ 1));

            unsigned* Ah = smemu + stg * STG_U32;
            unsigned* Al = Ah + 2560;
            unsigned* Bh = Ah + 5120;
            unsigned* Bl = Ah + 7296;

            #pragma unroll
            for (int p = 0; p < 4; p++) {
                const int r = p * 32 + arow2;
                #pragma unroll
                for (int cix = 0; cix < 2; cix++) {
                    const int idx = acc + cix * 4;
                    float v[4] = {av[p][cix].x, av[p][cix].y, av[p][cix].z, av[p][cix].w};
                    float hf[4], lf[4];
                    #pragma unroll
                    for (int i = 0; i < 4; i++) {
                        hf[i] = __bfloat162float(__float2bfloat16(v[i]));
                        lf[i] = v[i] - hf[i];
                    }
                    Ah[r * 20 + idx * 2]     = packbf(hf[0], hf[1]);
                    Ah[r * 20 + idx * 2 + 1] = packbf(hf[2], hf[3]);
                    Al[r * 20 + idx * 2]     = packbf(lf[0], lf[1]);
                    Al[r * 20 + idx * 2 + 1] = packbf(lf[2], lf[3]);
                }
            }
            #pragma unroll
            for (int p = 0; p < 4; p++) {
                const int q = p * 4 + bq2;
                float v0[4] = {bv[p][0].x, bv[p][0].y, bv[p][0].z, bv[p][0].w};
                float v1[4] = {bv[p][1].x, bv[p][1].y, bv[p][1].z, bv[p][1].w};
                #pragma unroll
                for (int i = 0; i < 4; i++) {
                    float h0 = __bfloat162float(__float2bfloat16(v0[i]));
                    float h1 = __bfloat162float(__float2bfloat16(v1[i]));
                    Bh[q * 136 + bc4 * 4 + i] = packbf(h0, h1);
                    Bl[q * 136 + bc4 * 4 + i] = packbf(v0[i] - h0, v1[i] - h1);
                }
            }

            mbar_arrive(bar0 + stg * 8);
            if (++stg == 3) { stg = 0; par ^= 1; }
        }
    }
}

// ---------------------------------------------------------------------------
// 5) Fused attention (R16, measured): 512 threads, 4-row blocking per warp.
// ---------------------------------------------------------------------------
constexpr int ATTN_SMEM = 55968 * 4;   // 223872 B

__global__ __launch_bounds__(512) void attn_kernel() {
    extern __shared__ float sm[];
    float* Ks = sm;                      // [257][65]
    float* Vs = sm + 16720;              // [257][65]
    float* Q4 = sm + 33440;              // [16 warps][64 k][4 rows]
    float* P4 = sm + 37536;              // [16 warps][288 j][4 rows]

    const int b = blockIdx.x / kNH, hh = blockIdx.x % kNH;
    const int tid = threadIdx.x, w = tid >> 5, lane = tid & 31;
    const float* base = g_qkv + (size_t)b * kN * kQKV + hh * kHD;

    for (int i = tid; i < kN * kHD; i += 512) {
        const int n = i >> 6, d = i & 63;
        Ks[n * 65 + d] = base[(size_t)n * kQKV + kD + d];
        Vs[n * 65 + d] = base[(size_t)n * kQKV + 2 * kD + d];
    }
    __syncthreads();

    float* Q4w = Q4 + w * 256;
    float* P4w = P4 + w * 1152;

    for (int pass = 0; pass < 5; pass++) {
        const int r0 = pass * 64 + w * 4;

        #pragma unroll
        for (int hk = 0; hk < 2; hk++) {
            const int k = hk * 32 + lane;
            #pragma unroll
            for (int rr = 0; rr < 4; rr++) {
                int r = r0 + rr; if (r >= kN) r = kN - 1;
                Q4w[k * 4 + rr] = base[(size_t)r * kQKV + k];
            }
        }
        __syncwarp();

        float s[4][9];
        #pragma unroll
        for (int t = 0; t < 9; t++) {
            const int j = t * 32 + lane;
            const int jj = (j < kN) ? j : 0;
            const float* kr = Ks + jj * 65;
            float a0 = 0.f, a1 = 0.f, a2 = 0.f, a3 = 0.f;
            #pragma unroll 16
            for (int k = 0; k < 64; k++) {
                const float kv = kr[k];
                const float4 qv = *(const float4*)(Q4w + k * 4);
                a0 += qv.x * kv; a1 += qv.y * kv;
                a2 += qv.z * kv; a3 += qv.w * kv;
            }
            const float ninf = -__int_as_float(0x7f800000);
            s[0][t] = (j < kN) ? a0 * 0.125f : ninf;
            s[1][t] = (j < kN) ? a1 * 0.125f : ninf;
            s[2][t] = (j < kN) ? a2 * 0.125f : ninf;
            s[3][t] = (j < kN) ? a3 * 0.125f : ninf;
        }

        #pragma unroll
        for (int rr = 0; rr < 4; rr++) {
            float mx = s[rr][0];
            #pragma unroll
            for (int t = 1; t < 9; t++) mx = fmaxf(mx, s[rr][t]);
            #pragma unroll
            for (int o = 16; o > 0; o >>= 1) mx = fmaxf(mx, __shfl_xor_sync(0xffffffffu, mx, o));
            float sum = 0.f;
            #pragma unroll
            for (int t = 0; t < 9; t++) { s[rr][t] = __expf(s[rr][t] - mx); sum += s[rr][t]; }
            #pragma unroll
            for (int o = 16; o > 0; o >>= 1) sum += __shfl_xor_sync(0xffffffffu, sum, o);
            const float inv = 1.0f / sum;
            #pragma unroll
            for (int t = 0; t < 9; t++) P4w[(t * 32 + lane) * 4 + rr] = s[rr][t] * inv;
        }
        __syncwarp();

        float o0[4] = {0.f, 0.f, 0.f, 0.f};
        float o1[4] = {0.f, 0.f, 0.f, 0.f};
        #pragma unroll 4
        for (int j = 0; j < kN; j++) {
            const float v0 = Vs[j * 65 + lane];
            const float v1 = Vs[j * 65 + 32 + lane];
            const float4 p = *(const float4*)(P4w + j * 4);
            o0[0] += p.x * v0; o1[0] += p.x * v1;
            o0[1] += p.y * v0; o1[1] += p.y * v1;
            o0[2] += p.z * v0; o1[2] += p.z * v1;
            o0[3] += p.w * v0; o1[3] += p.w * v1;
        }

        #pragma unroll
        for (int rr = 0; rr < 4; rr++) {
            const int r = r0 + rr;
            if (r < kN) {
                float* orow = g_att + (size_t)(b * kN + r) * kD + hh * kHD;
                orow[lane]      = o0[rr];
                orow[lane + 32] = o1[rr];
            }
        }
        __syncwarp();
    }
}

// ---------------------------------------------------------------------------
// 6) Head
// ---------------------------------------------------------------------------
__global__ void head_kernel(const float* __restrict__ hw, const float* __restrict__ hb,
                            float* __restrict__ out) {
    __shared__ float xs[kD];
    const int b = blockIdx.y;
    const int col = blockIdx.x * 256 + threadIdx.x;
    for (int i = threadIdx.x; i < kD; i += 256) xs[i] = g_cls[b * kD + i];
    __syncthreads();
    if (col < kNC) {
        float acc = hb[col];
        #pragma unroll 4
        for (int k = 0; k < kD; k++) acc += xs[k] * hw[(size_t)k * kNC + col];
        out[(size_t)b * kNC + col] = acc;
    }
}

// ---------------------------------------------------------------------------
// Launch
// ---------------------------------------------------------------------------
extern "C" void kernel_launch(void* const* d_in, const int* in_sizes, int n_in,
                              void* d_out, int out_size) {
    const float* img    = (const float*)d_in[0];
    const int*   seg    = (const int*)  d_in[1];
    const float* w_fe   = (const float*)d_in[2];
    const float* b_fe   = (const float*)d_in[3];
    const float* cls_t  = (const float*)d_in[4];
    const float* pos    = (const float*)d_in[5];
    const float* ln1_g  = (const float*)d_in[6];
    const float* ln1_b  = (const float*)d_in[7];
    const float* qkv_w  = (const float*)d_in[8];
    const float* qkv_b  = (const float*)d_in[9];
    const float* proj_w = (const float*)d_in[10];
    const float* proj_b = (const float*)d_in[11];
    const float* ln2_g  = (const float*)d_in[12];
    const float* ln2_b  = (const float*)d_in[13];
    const float* mlp_w1 = (const float*)d_in[14];
    const float* mlp_b1 = (const float*)d_in[15];
    const float* mlp_w2 = (const float*)d_in[16];
    const float* mlp_b2 = (const float*)d_in[17];
    const float* norm_g = (const float*)d_in[18];
    const float* norm_b = (const float*)d_in[19];
    const float* head_w = (const float*)d_in[20];
    const float* head_b = (const float*)d_in[21];

    cudaFuncSetAttribute(attn_kernel,    cudaFuncAttributeMaxDynamicSharedMemorySize, ATTN_SMEM);
    cudaFuncSetAttribute(gemm_kernel<0>, cudaFuncAttributeMaxDynamicSharedMemorySize, GEMM_SMEM);
    cudaFuncSetAttribute(gemm_kernel<1>, cudaFuncAttributeMaxDynamicSharedMemorySize, GEMM_SMEM);
    cudaFuncSetAttribute(gemm_kernel<2>, cudaFuncAttributeMaxDynamicSharedMemorySize, GEMM_SMEM);

    float *px, *ph, *pq, *pa, *pm, *pc;
    cudaGetSymbolAddress((void**)&px, g_x);
    cudaGetSymbolAddress((void**)&ph, g_h);
    cudaGetSymbolAddress((void**)&pq, g_qkv);
    cudaGetSymbolAddress((void**)&pa, g_att);
    cudaGetSymbolAddress((void**)&pm, g_mlp);
    cudaGetSymbolAddress((void**)&pc, g_cls);

    seg_sum_kernel<<<kB, 256>>>(img, seg);
    embed_kernel<<<kM, 256>>>(w_fe, b_fe, cls_t, pos);

    const dim3 gQKV(kQKV / 128, (kM + 127) / 128);
    const dim3 gD  (kD   / 128, (kM + 127) / 128);
    const dim3 gMLP(kMLP / 128, (kM + 127) / 128);

    for (int l = 0; l < kL; l++) {
        ln_kernel<<<kM, 256>>>(px, ph, ln1_g + (size_t)l * kD, ln1_b + (size_t)l * kD, kD, kD);
        gemm_kernel<0><<<gQKV, 384, GEMM_SMEM>>>(ph, qkv_w + (size_t)l * kD * kQKV,
                                                 qkv_b + (size_t)l * kQKV, nullptr, pq,
                                                 kM, kQKV, kD);
        attn_kernel<<<kB * kNH, 512, ATTN_SMEM>>>();
        gemm_kernel<2><<<gD, 384, GEMM_SMEM>>>(pa, proj_w + (size_t)l * kD * kD,
                                               proj_b + (size_t)l * kD, px, px,
                                               kM, kD, kD);
        ln_kernel<<<kM, 256>>>(px, ph, ln2_g + (size_t)l * kD, ln2_b + (size_t)l * kD, kD, kD);
        gemm_kernel<1><<<gMLP, 384, GEMM_SMEM>>>(ph, mlp_w1 + (size_t)l * kD * kMLP,
                                                 mlp_b1 + (size_t)l * kMLP, nullptr, pm,
                                                 kM, kMLP, kD);
        gemm_kernel<2><<<gD, 384, GEMM_SMEM>>>(pm, mlp_w2 + (size_t)l * kMLP * kD,
                                               mlp_b2 + (size_t)l * kD, px, px,
                                               kM, kD, kMLP);
    }

    // Final LN on cls rows only (row b lives at x + b*257*768), then head.
    ln_kernel<<<kB, 256>>>(px, pc, norm_g, norm_b, (long)kN * kD, (long)kD);
    head_kernel<<<dim3((kNC + 255) / 256, kB), 256>>>(head_w, head_b, (float*)d_out);
}